// round 1
// baseline (speedup 1.0000x reference)
#include <cuda_runtime.h>
#include <cstdint>

// PatchNeighborSearcher: B=8, H=W=16 (P=256), L=64, C=64.
// out[b, p, l*8+n, c] = in[b, p+off(n), l, c] if neighbor in-bounds else 0.
// Pure gather; one thread per output float4 (C=64 -> 16 float4 per row).
//
// Output linear float4 index layout (row-major):
//   idx = (((b*256 + p)*64 + l)*8 + n)*16 + c4
// All dims are powers of two -> shift/mask decode.

__global__ void __launch_bounds__(256) patch_neighbor_kernel(
    const float4* __restrict__ in, float4* __restrict__ out, int total4)
{
    int idx = blockIdx.x * blockDim.x + threadIdx.x;
    if (idx >= total4) return;

    int c4 = idx & 15;
    int n  = (idx >> 4) & 7;
    int l  = (idx >> 7) & 63;
    int p  = (idx >> 13) & 255;
    int b  = idx >> 21;

    int h = p >> 4;
    int w = p & 15;

    // neighbor n -> (dy, dx): skip the center cell of the 3x3 window
    int m  = n + (n >= 4 ? 1 : 0);   // 0..8 minus center(4)
    int dy = m / 3 - 1;
    int dx = m % 3 - 1;

    int hh = h + dy;
    int ww = w + dx;

    float4 v = make_float4(0.f, 0.f, 0.f, 0.f);
    if ((unsigned)hh < 16u && (unsigned)ww < 16u) {
        int pp = (hh << 4) | ww;
        // input float4 index: (((b*256 + pp)*64 + l)*16 + c4)
        int iidx = ((((b << 8) | pp) << 6 | l) << 4) | c4;
        v = in[iidx];
    }
    out[idx] = v;
}

extern "C" void kernel_launch(void* const* d_in, const int* in_sizes, int n_in,
                              void* d_out, int out_size)
{
    const float4* in = (const float4*)d_in[0];
    float4* out = (float4*)d_out;

    int total4 = out_size / 4;               // 16,777,216 for the given shapes
    int threads = 256;
    int blocks = (total4 + threads - 1) / threads;
    patch_neighbor_kernel<<<blocks, threads>>>(in, out, total4);
}

// round 2
// speedup vs baseline: 1.2477x; 1.2477x over previous
#include <cuda_runtime.h>
#include <cstdint>

// PatchNeighborSearcher: B=8, H=W=16 (P=256), L=64, C=64.
// out[b, p, l*8+n, c] = in[b, neighbor_p(n), l, c] if in-bounds else 0.
//
// One thread per (b,p,l,c4) produces all 8 neighbor float4 outputs.
// Input float4 index for (b,p,l,c4) is exactly tid:
//   tid = (b<<18) | (p<<10) | (l<<4) | c4
// Neighbor (dy,dx) shifts p by dy*16+dx -> input index tid + ((dy*16+dx)<<10),
// a compile-time constant per neighbor. Only validity depends on (h,w).
//
// Output float4 index: (b<<21)|(p<<13)|(l<<7)|(n<<4)|c4
//                    = ((tid & ~15) << 3) | (n<<4) | (tid & 15)

__global__ void __launch_bounds__(256) patch_neighbor_kernel(
    const float4* __restrict__ in, float4* __restrict__ out)
{
    int tid = blockIdx.x * blockDim.x + threadIdx.x;   // 2,097,152 threads

    int h = (tid >> 14) & 15;
    int w = (tid >> 10) & 15;

    bool hm = (h > 0);        // h-1 valid
    bool hp = (h < 15);       // h+1 valid
    bool wm = (w > 0);        // w-1 valid
    bool wp = (w < 15);       // w+1 valid

    // neighbor order: (-1,-1)(-1,0)(-1,1)(0,-1)(0,1)(1,-1)(1,0)(1,1)
    bool valid[8] = { hm && wm, hm, hm && wp,
                      wm,           wp,
                      hp && wm, hp, hp && wp };

    // input offset per neighbor, in float4 units: (dy*16 + dx) << 10
    constexpr int OFF[8] = {
        (-17) << 10, (-16) << 10, (-15) << 10,
        ( -1) << 10,               (  1) << 10,
        ( 15) << 10, ( 16) << 10, ( 17) << 10
    };

    const float4 zero = make_float4(0.f, 0.f, 0.f, 0.f);
    float4 v[8];

    // 8 independent predicated loads -> MLP=8
    #pragma unroll
    for (int n = 0; n < 8; n++) {
        v[n] = valid[n] ? __ldg(&in[tid + OFF[n]]) : zero;
    }

    int obase = ((tid & ~15) << 3) | (tid & 15);

    #pragma unroll
    for (int n = 0; n < 8; n++) {
        __stcs(&out[obase + (n << 4)], v[n]);
    }
}

extern "C" void kernel_launch(void* const* d_in, const int* in_sizes, int n_in,
                              void* d_out, int out_size)
{
    const float4* in = (const float4*)d_in[0];
    float4* out = (float4*)d_out;

    // total output float4 = out_size/4; threads = total/8
    int threads_total = (out_size / 4) / 8;     // 2,097,152
    int block = 256;
    int grid = (threads_total + block - 1) / block;
    patch_neighbor_kernel<<<grid, block>>>(in, out);
}